// round 4
// baseline (speedup 1.0000x reference)
#include <cuda_runtime.h>
#include <cuda_bf16.h>
#include <cstdint>
#include <cstddef>

#define LOG2E 1.4426950408889634f
#define LN2   0.6931471805599453f

// ---- static scratch ----
__device__ float g_cost[64 * 512 * 256];        // diag layout [b][i+j][j], log2e-scaled
__device__ float g_xn[64 * 256];                // log2e * |x_i|^2
__device__ float g_yn[64 * 256];
__device__ unsigned short g_xb[64 * 256 * 128]; // bf16 bits of x
__device__ unsigned short g_yb[64 * 256 * 128]; // bf16 bits of y

__device__ __forceinline__ float ex2f(float x) {
    float y; asm("ex2.approx.f32 %0, %1;" : "=f"(y) : "f"(x)); return y;
}
__device__ __forceinline__ float lg2f(float x) {
    float y; asm("lg2.approx.f32 %0, %1;" : "=f"(y) : "f"(x)); return y;
}
__device__ __forceinline__ uint32_t sptr(const void* p) {
    return (uint32_t)__cvta_generic_to_shared(p);
}

// ================= K0: norms + bf16 convert (warp per row) =================
__global__ void __launch_bounds__(256) prep_kernel(const float* __restrict__ x,
                                                   const float* __restrict__ y,
                                                   float* __restrict__ out) {
    int gw = blockIdx.x * 8 + (threadIdx.x >> 5);
    int lane = threadIdx.x & 31;
    bool isx = gw < 16384;
    int rowg = isx ? gw : gw - 16384;  // b*256 + r
    const float* src = (isx ? x : y) + (size_t)rowg * 128 + lane * 4;
    float4 f = *(const float4*)src;
    float s = f.x * f.x;
    s = fmaf(f.y, f.y, s); s = fmaf(f.z, f.z, s); s = fmaf(f.w, f.w, s);
#pragma unroll
    for (int off = 16; off >= 1; off >>= 1) s += __shfl_xor_sync(0xffffffffu, s, off);
    if (lane == 0) (isx ? g_xn : g_yn)[rowg] = s * LOG2E;
    ushort4 s4;
    s4.x = __bfloat16_as_ushort(__float2bfloat16(f.x));
    s4.y = __bfloat16_as_ushort(__float2bfloat16(f.y));
    s4.z = __bfloat16_as_ushort(__float2bfloat16(f.z));
    s4.w = __bfloat16_as_ushort(__float2bfloat16(f.w));
    *(ushort4*)((isx ? g_xb : g_yb) + (size_t)rowg * 128 + lane * 4) = s4;
    if (blockIdx.x == 0 && threadIdx.x == 0) out[0] = 0.f;
}

// ================= K1: bf16 mma cost GEMM, diag-coalesced epilogue =================
// 256 blocks = 64 batches x (2x2 tiles of 128x128). 8 warps, warp tile 32(m) x 64(n).
__global__ void __launch_bounds__(256) cost_gemm_kernel() {
    __shared__ __align__(16) char smraw[33280];
    unsigned short* Xs = (unsigned short*)smraw;       // [128][64] bf16, swizzled
    unsigned short* Ys = Xs + 128 * 64;
    float* Cs = (float*)smraw;                          // [64][130]

    int bx = blockIdx.x;
    int b = bx >> 2, tm = (bx >> 1) & 1, tn = bx & 1;
    int t = threadIdx.x, lane = t & 31, w = t >> 5;
    int wr = w >> 1, wc = w & 1;

    const unsigned short* Xg = g_xb + ((size_t)(b * 256 + tm * 128)) * 128;
    const unsigned short* Yg = g_yb + ((size_t)(b * 256 + tn * 128)) * 128;

    float acc[2][8][4];
#pragma unroll
    for (int am = 0; am < 2; am++)
#pragma unroll
        for (int bn = 0; bn < 8; bn++)
#pragma unroll
            for (int k = 0; k < 4; k++) acc[am][bn][k] = 0.f;

    int arow0 = 32 * wr + (lane & 15);
    int ahalf = lane >> 4;
    int brow0 = 64 * wc + (lane & 7) + ((lane >> 4) << 3);
    int bhalf = (lane >> 3) & 1;

    for (int kc = 0; kc < 128; kc += 64) {
        __syncthreads();
#pragma unroll
        for (int p = 0; p < 4; p++) {
            int u = t + 256 * p;
            int row = u >> 3, c16 = u & 7;
            uint4 vx = *(const uint4*)(Xg + (size_t)row * 128 + kc + c16 * 8);
            uint4 vy = *(const uint4*)(Yg + (size_t)row * 128 + kc + c16 * 8);
            int soff = row * 128 + ((c16 ^ (row & 7)) << 4);
            *(uint4*)((char*)Xs + soff) = vx;
            *(uint4*)((char*)Ys + soff) = vy;
        }
        __syncthreads();
#pragma unroll
        for (int ks = 0; ks < 4; ks++) {
            uint32_t a[2][4], bf[8][2];
#pragma unroll
            for (int am = 0; am < 2; am++) {
                int row = arow0 + 16 * am;
                int kb16 = ks * 2 + ahalf;
                uint32_t ad = sptr((char*)Xs + row * 128 + ((kb16 ^ (row & 7)) << 4));
                asm volatile("ldmatrix.sync.aligned.m8n8.x4.shared.b16 {%0,%1,%2,%3},[%4];"
                    : "=r"(a[am][0]), "=r"(a[am][1]), "=r"(a[am][2]), "=r"(a[am][3]) : "r"(ad));
            }
#pragma unroll
            for (int bp = 0; bp < 4; bp++) {
                int row = brow0 + 16 * bp;
                int kb16 = ks * 2 + bhalf;
                uint32_t ad = sptr((char*)Ys + row * 128 + ((kb16 ^ (row & 7)) << 4));
                asm volatile("ldmatrix.sync.aligned.m8n8.x4.shared.b16 {%0,%1,%2,%3},[%4];"
                    : "=r"(bf[2 * bp][0]), "=r"(bf[2 * bp][1]),
                      "=r"(bf[2 * bp + 1][0]), "=r"(bf[2 * bp + 1][1]) : "r"(ad));
            }
#pragma unroll
            for (int am = 0; am < 2; am++)
#pragma unroll
                for (int bn = 0; bn < 8; bn++)
                    asm volatile("mma.sync.aligned.m16n8k16.row.col.f32.bf16.bf16.f32 "
                        "{%0,%1,%2,%3},{%4,%5,%6,%7},{%8,%9},{%0,%1,%2,%3};"
                        : "+f"(acc[am][bn][0]), "+f"(acc[am][bn][1]),
                          "+f"(acc[am][bn][2]), "+f"(acc[am][bn][3])
                        : "r"(a[am][0]), "r"(a[am][1]), "r"(a[am][2]), "r"(a[am][3]),
                          "r"(bf[bn][0]), "r"(bf[bn][1]));
        }
    }

    // epilogue: stage to smem in 2 row-halves, then coalesced diag-major stores
    __syncthreads();
    float* cb = g_cost + (size_t)b * 512 * 256;
    const float* xn = g_xn + b * 256;
    const float* yn = g_yn + b * 256;

#pragma unroll
    for (int h = 0; h < 2; h++) {
        if ((wr >> 1) == h) {
            int rbase = 32 * (wr & 1);
#pragma unroll
            for (int am = 0; am < 2; am++)
#pragma unroll
                for (int bn = 0; bn < 8; bn++) {
                    int rr = rbase + 16 * am + (lane >> 2);
                    int cc = 64 * wc + 8 * bn + 2 * (lane & 3);
                    *(float2*)&Cs[rr * 130 + cc] = make_float2(acc[am][bn][0], acc[am][bn][1]);
                    *(float2*)&Cs[(rr + 8) * 130 + cc] = make_float2(acc[am][bn][2], acc[am][bn][3]);
                }
        }
        __syncthreads();
        int tt = t & 127;
        for (int s2 = 0; s2 < 192; s2 += 2) {
            int s = s2 + (t >> 7);                 // local diag within half: 0..191
            int lj_lo = max(0, s - 63), lj_hi = min(127, s);
            int lj = lj_lo + tt;
            if (s < 191 && lj <= lj_hi) {
                int li = s - lj;
                int i = tm * 128 + 64 * h + li;
                int j = tn * 128 + lj;
                float v = xn[i] + yn[j] - (2.0f * LOG2E) * Cs[li * 130 + lj];
                cb[(size_t)(i + j) * 256 + j] = v;
            }
        }
        __syncthreads();
    }
}

// ================= K2: barrier-free warp-pipelined soft-DTW =================
// One block per batch, 8 warps, thread t owns column j=t+1. Warps self-pipeline;
// cross-warp handoff via 64-bit {stamp,value} smem mailboxes (written once each).
__global__ void __launch_bounds__(256) dp_kernel(float* __restrict__ out) {
    __shared__ unsigned long long mb[7][256];
    int t = threadIdx.x, lane = t & 31, w = t >> 5, b = blockIdx.x;
    for (int idx = t; idx < 7 * 256; idx += 256) ((unsigned long long*)mb)[idx] = 0ull;
    __syncthreads();

    const float INF = __int_as_float(0x7f800000);
    const float* cost = g_cost + (size_t)b * 512 * 256;

    int ds = 32 * w + 2, de = 32 * w + 288;
    int jcol = t + 1;
    float r1 = INF, r2 = INF;   // own R at d-1, d-2
    float cmb = INF;            // lane0 mailbox carry (diag term)

    float cp0 = cost[(size_t)(ds - 2) * 256 + t];
    float cp1 = cost[(size_t)(ds - 1) * 256 + t];

    uint32_t cons_base = (w > 0) ? sptr(&mb[w - 1][0]) : 0u;
    uint32_t prod_base = (w < 7) ? sptr(&mb[w][0]) : 0u;

    for (int d = ds; d <= de; ++d) {
        float ccur = cp0; cp0 = cp1;
        if (d <= 510) cp1 = cost[(size_t)d * 256 + t];

        float bbv = __shfl_up_sync(0xffffffffu, r1, 1);
        float cv  = __shfl_up_sync(0xffffffffu, r2, 1);

        int i = d - jcol;
        bool act = (i >= 1) && (i <= 256);

        if (lane == 0) {
            if (w == 0) {
                bbv = INF;
                cv = (d == 2) ? 0.0f : INF;
            } else if (act) {
                unsigned want = (unsigned)(d - 1);
                uint32_t addr = cons_base + ((unsigned)(d - 32 * w - 2) << 3);
                unsigned long long v;
                do {
                    asm volatile("ld.volatile.shared.u64 %0, [%1];" : "=l"(v) : "r"(addr));
                } while ((unsigned)(v >> 32) != want);
                bbv = __int_as_float((int)(unsigned)(v & 0xffffffffu));
                cv = cmb; cmb = bbv;
            }
        }

        float av = r1;
        // softmin3 in log2 domain: lo - lg2(1 + ex2(lo-mid) + ex2(lo-hi))
        float mn = fminf(av, bbv), mx = fmaxf(av, bbv);
        float lo  = fminf(mn, cv);
        float mid = fmaxf(mn, fminf(mx, cv));
        float hi  = fmaxf(mx, cv);
        float ssum = 1.0f + ex2f(lo - mid) + ex2f(lo - hi);
        float rn = ccur + lo - lg2f(ssum);

        r2 = r1;
        if (act) r1 = rn;

        if (w < 7 && lane == 31 && act) {
            unsigned long long pk = ((unsigned long long)(unsigned)d << 32)
                                  | (unsigned)__float_as_uint(r1);
            uint32_t addr = prod_base + ((unsigned)(d - 32 * w - 33) << 3);
            asm volatile("st.volatile.shared.u64 [%0], %1;" :: "r"(addr), "l"(pk));
        }
    }

    if (t == 255) atomicAdd(out, r1 * (LN2 / 64.0f));
}

extern "C" void kernel_launch(void* const* d_in, const int* in_sizes, int n_in,
                              void* d_out, int out_size) {
    const float* x = (const float*)d_in[0];
    const float* y = (const float*)d_in[1];
    float* out = (float*)d_out;
    prep_kernel<<<4096, 256>>>(x, y, out);
    cost_gemm_kernel<<<256, 256>>>();
    dp_kernel<<<64, 256>>>(out);
}

// round 5
// speedup vs baseline: 2.0522x; 2.0522x over previous
#include <cuda_runtime.h>
#include <cuda_bf16.h>
#include <cstdint>
#include <cstddef>

#define LOG2E 1.4426950408889634f
#define LN2   0.6931471805599453f

// ---- static scratch ----
__device__ float g_cost[64 * 512 * 256];        // diag layout [b][i+j][j], log2e-scaled
__device__ float g_xn[64 * 256];                // log2e * |x_i|^2
__device__ float g_yn[64 * 256];
__device__ unsigned short g_xb[64 * 256 * 128]; // bf16 bits of x
__device__ unsigned short g_yb[64 * 256 * 128]; // bf16 bits of y

__device__ __forceinline__ float ex2f(float x) {
    float y; asm("ex2.approx.f32 %0, %1;" : "=f"(y) : "f"(x)); return y;
}
__device__ __forceinline__ float lg2f(float x) {
    float y; asm("lg2.approx.f32 %0, %1;" : "=f"(y) : "f"(x)); return y;
}
__device__ __forceinline__ uint32_t sptr(const void* p) {
    return (uint32_t)__cvta_generic_to_shared(p);
}

// ================= K0: norms + bf16 convert (warp per row) =================
__global__ void __launch_bounds__(256) prep_kernel(const float* __restrict__ x,
                                                   const float* __restrict__ y,
                                                   float* __restrict__ out) {
    int gw = blockIdx.x * 8 + (threadIdx.x >> 5);
    int lane = threadIdx.x & 31;
    bool isx = gw < 16384;
    int rowg = isx ? gw : gw - 16384;  // b*256 + r
    const float* src = (isx ? x : y) + (size_t)rowg * 128 + lane * 4;
    float4 f = *(const float4*)src;
    float s = f.x * f.x;
    s = fmaf(f.y, f.y, s); s = fmaf(f.z, f.z, s); s = fmaf(f.w, f.w, s);
#pragma unroll
    for (int off = 16; off >= 1; off >>= 1) s += __shfl_xor_sync(0xffffffffu, s, off);
    if (lane == 0) (isx ? g_xn : g_yn)[rowg] = s * LOG2E;
    ushort4 s4;
    s4.x = __bfloat16_as_ushort(__float2bfloat16(f.x));
    s4.y = __bfloat16_as_ushort(__float2bfloat16(f.y));
    s4.z = __bfloat16_as_ushort(__float2bfloat16(f.z));
    s4.w = __bfloat16_as_ushort(__float2bfloat16(f.w));
    *(ushort4*)((isx ? g_xb : g_yb) + (size_t)rowg * 128 + lane * 4) = s4;
    if (blockIdx.x == 0 && threadIdx.x == 0) out[0] = 0.f;
}

// ================= K1: bf16 mma cost GEMM, diag-coalesced epilogue =================
// 256 blocks = 64 batches x (2x2 tiles of 128x128). 8 warps, warp tile 32(m) x 64(n).
__global__ void __launch_bounds__(256) cost_gemm_kernel() {
    __shared__ __align__(16) char smraw[33280];
    unsigned short* Xs = (unsigned short*)smraw;       // [128][64] bf16, swizzled
    unsigned short* Ys = Xs + 128 * 64;
    float* Cs = (float*)smraw;                          // [64][130]

    int bx = blockIdx.x;
    int b = bx >> 2, tm = (bx >> 1) & 1, tn = bx & 1;
    int t = threadIdx.x, lane = t & 31, w = t >> 5;
    int wr = w >> 1, wc = w & 1;

    const unsigned short* Xg = g_xb + ((size_t)(b * 256 + tm * 128)) * 128;
    const unsigned short* Yg = g_yb + ((size_t)(b * 256 + tn * 128)) * 128;

    float acc[2][8][4];
#pragma unroll
    for (int am = 0; am < 2; am++)
#pragma unroll
        for (int bn = 0; bn < 8; bn++)
#pragma unroll
            for (int k = 0; k < 4; k++) acc[am][bn][k] = 0.f;

    int arow0 = 32 * wr + (lane & 15);
    int ahalf = lane >> 4;
    int brow0 = 64 * wc + (lane & 7) + ((lane >> 4) << 3);
    int bhalf = (lane >> 3) & 1;

    for (int kc = 0; kc < 128; kc += 64) {
        __syncthreads();
#pragma unroll
        for (int p = 0; p < 4; p++) {
            int u = t + 256 * p;
            int row = u >> 3, c16 = u & 7;
            uint4 vx = *(const uint4*)(Xg + (size_t)row * 128 + kc + c16 * 8);
            uint4 vy = *(const uint4*)(Yg + (size_t)row * 128 + kc + c16 * 8);
            int soff = row * 128 + ((c16 ^ (row & 7)) << 4);
            *(uint4*)((char*)Xs + soff) = vx;
            *(uint4*)((char*)Ys + soff) = vy;
        }
        __syncthreads();
#pragma unroll
        for (int ks = 0; ks < 4; ks++) {
            uint32_t a[2][4], bf[8][2];
#pragma unroll
            for (int am = 0; am < 2; am++) {
                int row = arow0 + 16 * am;
                int kb16 = ks * 2 + ahalf;
                uint32_t ad = sptr((char*)Xs + row * 128 + ((kb16 ^ (row & 7)) << 4));
                asm volatile("ldmatrix.sync.aligned.m8n8.x4.shared.b16 {%0,%1,%2,%3},[%4];"
                    : "=r"(a[am][0]), "=r"(a[am][1]), "=r"(a[am][2]), "=r"(a[am][3]) : "r"(ad));
            }
#pragma unroll
            for (int bp = 0; bp < 4; bp++) {
                int row = brow0 + 16 * bp;
                int kb16 = ks * 2 + bhalf;
                uint32_t ad = sptr((char*)Ys + row * 128 + ((kb16 ^ (row & 7)) << 4));
                asm volatile("ldmatrix.sync.aligned.m8n8.x4.shared.b16 {%0,%1,%2,%3},[%4];"
                    : "=r"(bf[2 * bp][0]), "=r"(bf[2 * bp][1]),
                      "=r"(bf[2 * bp + 1][0]), "=r"(bf[2 * bp + 1][1]) : "r"(ad));
            }
#pragma unroll
            for (int am = 0; am < 2; am++)
#pragma unroll
                for (int bn = 0; bn < 8; bn++)
                    asm volatile("mma.sync.aligned.m16n8k16.row.col.f32.bf16.bf16.f32 "
                        "{%0,%1,%2,%3},{%4,%5,%6,%7},{%8,%9},{%0,%1,%2,%3};"
                        : "+f"(acc[am][bn][0]), "+f"(acc[am][bn][1]),
                          "+f"(acc[am][bn][2]), "+f"(acc[am][bn][3])
                        : "r"(a[am][0]), "r"(a[am][1]), "r"(a[am][2]), "r"(a[am][3]),
                          "r"(bf[bn][0]), "r"(bf[bn][1]));
        }
    }

    // epilogue: stage to smem in 2 row-halves, then coalesced diag-major stores
    __syncthreads();
    float* cb = g_cost + (size_t)b * 512 * 256;
    const float* xn = g_xn + b * 256;
    const float* yn = g_yn + b * 256;

#pragma unroll
    for (int h = 0; h < 2; h++) {
        if ((wr >> 1) == h) {
            int rbase = 32 * (wr & 1);
#pragma unroll
            for (int am = 0; am < 2; am++)
#pragma unroll
                for (int bn = 0; bn < 8; bn++) {
                    int rr = rbase + 16 * am + (lane >> 2);
                    int cc = 64 * wc + 8 * bn + 2 * (lane & 3);
                    *(float2*)&Cs[rr * 130 + cc] = make_float2(acc[am][bn][0], acc[am][bn][1]);
                    *(float2*)&Cs[(rr + 8) * 130 + cc] = make_float2(acc[am][bn][2], acc[am][bn][3]);
                }
        }
        __syncthreads();
        int tt = t & 127;
        for (int s2 = 0; s2 < 192; s2 += 2) {
            int s = s2 + (t >> 7);                 // local diag within half: 0..191
            int lj_lo = max(0, s - 63), lj_hi = min(127, s);
            int lj = lj_lo + tt;
            if (s < 191 && lj <= lj_hi) {
                int li = s - lj;
                int i = tm * 128 + 64 * h + li;
                int j = tn * 128 + lj;
                float v = xn[i] + yn[j] - (2.0f * LOG2E) * Cs[li * 130 + lj];
                cb[(size_t)(i + j) * 256 + j] = v;
            }
        }
        __syncthreads();
    }
}

// ================= K2: warp-per-batch soft-DTW (no sync primitives) =================
// One warp per batch. Lane l owns columns j = 8l+1 .. 8l+8 (1-indexed DP).
// Global anti-diagonal d = i+j runs 2..512; all cross-lane traffic = 2 shfl/step.
__global__ void __launch_bounds__(32) dp_kernel(float* __restrict__ out) {
    int lane = threadIdx.x, b = blockIdx.x;
    const float INF = __int_as_float(0x7f800000);
    const float* cost = g_cost + (size_t)b * 512 * 256 + lane * 8;

    float r1[8], r2[8];   // own R at d-1, d-2 per column
#pragma unroll
    for (int c = 0; c < 8; c++) { r1[c] = INF; r2[c] = INF; }

    // depth-2 cost prefetch (row r feeds step d = r+2)
    float4 p0a = *(const float4*)(cost + 0 * 256);
    float4 p0b = *(const float4*)(cost + 0 * 256 + 4);
    float4 p1a = *(const float4*)(cost + 1 * 256);
    float4 p1b = *(const float4*)(cost + 1 * 256 + 4);

    int jbase = 8 * lane + 1;   // first owned column

    for (int d = 2; d <= 512; ++d) {
        float cc[8];
        cc[0] = p0a.x; cc[1] = p0a.y; cc[2] = p0a.z; cc[3] = p0a.w;
        cc[4] = p0b.x; cc[5] = p0b.y; cc[6] = p0b.z; cc[7] = p0b.w;
        p0a = p1a; p0b = p1b;
        if (d <= 510) {
            p1a = *(const float4*)(cost + (size_t)d * 256);
            p1b = *(const float4*)(cost + (size_t)d * 256 + 4);
        }

        // boundary values from lane l-1's last column (as of end of step d-1)
        float lb1 = __shfl_up_sync(0xffffffffu, r1[7], 1);
        float lb2 = __shfl_up_sync(0xffffffffu, r2[7], 1);
        if (lane == 0) { lb1 = INF; lb2 = (d == 2) ? 0.0f : INF; }

        // descending c: reads of index c-1 see previous-step values
#pragma unroll
        for (int c = 7; c >= 0; --c) {
            float up   = r1[c];
            float left = c ? r1[c - 1] : lb1;
            float dg   = c ? r2[c - 1] : lb2;
            float mn = fminf(up, left), mx = fmaxf(up, left);
            float lo  = fminf(mn, dg);
            float mid = fmaxf(mn, fminf(mx, dg));
            float hi  = fmaxf(mx, dg);
            float rn = cc[c] + lo - lg2f(1.0f + ex2f(lo - mid) + ex2f(lo - hi));
            unsigned im1 = (unsigned)(d - (jbase + c)) - 1u;  // i-1
            r2[c] = r1[c];
            if (im1 < 256u) r1[c] = rn;   // active: 1 <= i <= 256
        }
    }

    if (lane == 31) atomicAdd(out, r1[7] * (LN2 / 64.0f));
}

extern "C" void kernel_launch(void* const* d_in, const int* in_sizes, int n_in,
                              void* d_out, int out_size) {
    const float* x = (const float*)d_in[0];
    const float* y = (const float*)d_in[1];
    float* out = (float*)d_out;
    prep_kernel<<<4096, 256>>>(x, y, out);
    cost_gemm_kernel<<<256, 256>>>();
    dp_kernel<<<64, 32>>>(out);
}